// round 1
// baseline (speedup 1.0000x reference)
#include <cuda_runtime.h>
#include <math.h>

#define NDIM 512
#define C 128
#define NN (NDIM*NDIM)        // 262144 rows
#define PLANE NN

// Scratch (device globals; no allocation allowed in kernel_launch)
__device__ float g_icm[C * NN];   // i, channel-major: [c][i*512 + k]
__device__ float g_jcm[C * NN];   // j, channel-major: [c][j*512 + k]
__device__ float g_ecm[C * NN];   // einsum out, channel-major: [c][i*512 + j]
__device__ float g_sg [NN * C];   // sigmoid(x@Ws+bs), row-major

// ---------------------------------------------------------------------------
// helpers
// ---------------------------------------------------------------------------

__device__ __forceinline__ float sigmoidf_(float x) {
    return 1.0f / (1.0f + __expf(-x));
}

// Load one 128x64 column-tile of a 128x128 weight into smem Bs[k][c], ld=68
__device__ __forceinline__ void load_w(const float* __restrict__ W, int cbase,
                                       float* Bs, int tid) {
    #pragma unroll
    for (int i = 0; i < 8; ++i) {
        int f4 = tid + i * 256;      // 0..2047
        int k  = f4 >> 4;            // 0..127
        int c4 = (f4 & 15) << 2;     // 0..60
        float4 w = *(const float4*)(W + k * C + cbase + c4);
        *(float4*)(Bs + k * 68 + c4) = w;
    }
}

// C[64x64] += A[128x64 (k-major)] * B[128x64 (k-major)], 4x4 micro per thread
__device__ __forceinline__ void mm128(const float* __restrict__ Xs,
                                      const float* __restrict__ Bs,
                                      int tx, int ty, float acc[16]) {
    #pragma unroll 8
    for (int k = 0; k < 128; ++k) {
        float4 a = *(const float4*)(Xs + k * 68 + ty * 4);
        float4 b = *(const float4*)(Bs + k * 68 + tx * 4);
        acc[ 0] += a.x * b.x; acc[ 1] += a.x * b.y; acc[ 2] += a.x * b.z; acc[ 3] += a.x * b.w;
        acc[ 4] += a.y * b.x; acc[ 5] += a.y * b.y; acc[ 6] += a.y * b.z; acc[ 7] += a.y * b.w;
        acc[ 8] += a.z * b.x; acc[ 9] += a.z * b.y; acc[10] += a.z * b.z; acc[11] += a.z * b.w;
        acc[12] += a.w * b.x; acc[13] += a.w * b.y; acc[14] += a.w * b.z; acc[15] += a.w * b.w;
    }
}

// (Xs @ W1 + b1) * sigmoid(Xs @ W2 + b2) * mask  -> channel-major outcm
__device__ __forceinline__ void dual_glu(const float* __restrict__ Xs, float* Bs,
                                         const float* __restrict__ W1, const float* __restrict__ bv1,
                                         const float* __restrict__ W2, const float* __restrict__ bv2,
                                         const float* __restrict__ mask,
                                         float* __restrict__ outcm,
                                         int rowbase, int cbase, int tid, int tx, int ty) {
    float acc1[16], acc2[16];
    #pragma unroll
    for (int t = 0; t < 16; ++t) { acc1[t] = 0.f; acc2[t] = 0.f; }

    load_w(W1, cbase, Bs, tid);
    __syncthreads();
    mm128(Xs, Bs, tx, ty, acc1);
    __syncthreads();
    load_w(W2, cbase, Bs, tid);
    __syncthreads();
    mm128(Xs, Bs, tx, ty, acc2);
    __syncthreads();

    // epilogue -> transpose buffer T[64][65] aliased on Bs
    #pragma unroll
    for (int rr = 0; rr < 4; ++rr) {
        float m = __ldg(mask + rowbase + ty * 4 + rr);
        #pragma unroll
        for (int cc = 0; cc < 4; ++cc) {
            int c = cbase + tx * 4 + cc;
            float p = acc1[rr * 4 + cc] + __ldg(bv1 + c);
            float q = acc2[rr * 4 + cc] + __ldg(bv2 + c);
            Bs[(tx * 4 + cc) * 65 + ty * 4 + rr] = p * sigmoidf_(q) * m;
        }
    }
    __syncthreads();
    // coalesced channel-major store
    #pragma unroll
    for (int i = 0; i < 16; ++i) {
        int idx = tid + i * 256;
        int c = idx >> 6, r = idx & 63;
        outcm[(size_t)(cbase + c) * PLANE + rowbase + r] = Bs[c * 65 + r];
    }
    __syncthreads();
}

// ---------------------------------------------------------------------------
// Stage 1: LN(x2d) then 5 GEMMs (i-pair, j-pair, sigmoid gate)
// grid (4096, 2), block 256, dyn smem 2*128*68*4 = 69632 B
// ---------------------------------------------------------------------------
extern __shared__ float smem_[];

__global__ void __launch_bounds__(256)
stage1_kernel(const float* __restrict__ x2d, const float* __restrict__ mask,
              const float* __restrict__ ga1, const float* __restrict__ be1,
              const float* __restrict__ Wi,  const float* __restrict__ bi,
              const float* __restrict__ Wis, const float* __restrict__ bis,
              const float* __restrict__ Wj,  const float* __restrict__ bj,
              const float* __restrict__ Wjs, const float* __restrict__ bjs,
              const float* __restrict__ Ws,  const float* __restrict__ bs) {
    float* Xs = smem_;              // [128][68] k-major normalized x tile
    float* Bs = smem_ + 128 * 68;   // [128][68] weight tile / transpose buffer
    int tid = threadIdx.x;
    int tx = tid & 15, ty = tid >> 4;
    int rowbase = blockIdx.x * 64;
    int cbase   = blockIdx.y * 64;

    // ---- layernorm load: 4 threads per row, each owns 32 channels ----
    {
        int r = tid >> 2, e = tid & 3;
        const float* xr = x2d + (size_t)(rowbase + r) * C + e * 32;
        float v[32];
        float s = 0.f, ss = 0.f;
        #pragma unroll
        for (int t = 0; t < 8; ++t) {
            float4 f = *(const float4*)(xr + t * 4);
            v[t*4+0] = f.x; v[t*4+1] = f.y; v[t*4+2] = f.z; v[t*4+3] = f.w;
            s  += f.x + f.y + f.z + f.w;
            ss += f.x*f.x + f.y*f.y + f.z*f.z + f.w*f.w;
        }
        s  += __shfl_xor_sync(0xffffffffu, s, 1);
        s  += __shfl_xor_sync(0xffffffffu, s, 2);
        ss += __shfl_xor_sync(0xffffffffu, ss, 1);
        ss += __shfl_xor_sync(0xffffffffu, ss, 2);
        float mu = s * (1.0f / C);
        float rs = rsqrtf(ss * (1.0f / C) - mu * mu + 1e-5f);
        #pragma unroll
        for (int t = 0; t < 32; ++t) {
            int k = e * 32 + t;
            Xs[k * 68 + r] = (v[t] - mu) * rs * __ldg(ga1 + k) + __ldg(be1 + k);
        }
    }
    __syncthreads();

    // i = (x@Wi+bi) * sigmoid(x@Wis+bis) * mask   -> g_icm
    dual_glu(Xs, Bs, Wi,  bi,  Wis, bis, mask, g_icm, rowbase, cbase, tid, tx, ty);
    // j = (x@Wj+bj) * sigmoid(x@Wjs+bjs) * mask   -> g_jcm
    dual_glu(Xs, Bs, Wj,  bj,  Wjs, bjs, mask, g_jcm, rowbase, cbase, tid, tx, ty);

    // sg = sigmoid(x@Ws+bs) -> row-major
    {
        float acc[16];
        #pragma unroll
        for (int t = 0; t < 16; ++t) acc[t] = 0.f;
        load_w(Ws, cbase, Bs, tid);
        __syncthreads();
        mm128(Xs, Bs, tx, ty, acc);
        #pragma unroll
        for (int rr = 0; rr < 4; ++rr) {
            int row = rowbase + ty * 4 + rr;
            int c0 = cbase + tx * 4;
            float4 o;
            o.x = sigmoidf_(acc[rr*4+0] + __ldg(bs + c0 + 0));
            o.y = sigmoidf_(acc[rr*4+1] + __ldg(bs + c0 + 1));
            o.z = sigmoidf_(acc[rr*4+2] + __ldg(bs + c0 + 2));
            o.w = sigmoidf_(acc[rr*4+3] + __ldg(bs + c0 + 3));
            *(float4*)(g_sg + (size_t)row * C + c0) = o;
        }
    }
}

// ---------------------------------------------------------------------------
// Stage 2: out_c = I_c @ J_c^T   (128 batched 512x512x512 NT SGEMMs)
// grid (8, 8, 128), block 256
// ---------------------------------------------------------------------------
__global__ void __launch_bounds__(256)
einsum_kernel() {
    __shared__ float As[32 * 68];
    __shared__ float Bs[32 * 68];
    int tid = threadIdx.x;
    int tx = tid & 15, ty = tid >> 4;
    int ibase = blockIdx.x * 64, jbase = blockIdx.y * 64;
    int c = blockIdx.z;

    const float* A = g_icm + (size_t)c * PLANE + (size_t)ibase * NDIM;
    const float* B = g_jcm + (size_t)c * PLANE + (size_t)jbase * NDIM;

    float acc[16];
    #pragma unroll
    for (int t = 0; t < 16; ++t) acc[t] = 0.f;

    int lrow = tid >> 3;         // 0..31
    int lk4  = (tid & 7) * 4;    // 0..28

    for (int kb = 0; kb < NDIM; kb += 32) {
        #pragma unroll
        for (int m = 0; m < 2; ++m) {
            int row = lrow + m * 32;
            float4 a = *(const float4*)(A + (size_t)row * NDIM + kb + lk4);
            As[(lk4+0)*68 + row] = a.x;
            As[(lk4+1)*68 + row] = a.y;
            As[(lk4+2)*68 + row] = a.z;
            As[(lk4+3)*68 + row] = a.w;
            float4 b = *(const float4*)(B + (size_t)row * NDIM + kb + lk4);
            Bs[(lk4+0)*68 + row] = b.x;
            Bs[(lk4+1)*68 + row] = b.y;
            Bs[(lk4+2)*68 + row] = b.z;
            Bs[(lk4+3)*68 + row] = b.w;
        }
        __syncthreads();
        #pragma unroll
        for (int kk = 0; kk < 32; ++kk) {
            float4 a = *(const float4*)(As + kk * 68 + ty * 4);
            float4 b = *(const float4*)(Bs + kk * 68 + tx * 4);
            acc[ 0] += a.x*b.x; acc[ 1] += a.x*b.y; acc[ 2] += a.x*b.z; acc[ 3] += a.x*b.w;
            acc[ 4] += a.y*b.x; acc[ 5] += a.y*b.y; acc[ 6] += a.y*b.z; acc[ 7] += a.y*b.w;
            acc[ 8] += a.z*b.x; acc[ 9] += a.z*b.y; acc[10] += a.z*b.z; acc[11] += a.z*b.w;
            acc[12] += a.w*b.x; acc[13] += a.w*b.y; acc[14] += a.w*b.z; acc[15] += a.w*b.w;
        }
        __syncthreads();
    }

    float* O = g_ecm + (size_t)c * PLANE + (size_t)ibase * NDIM + jbase;
    #pragma unroll
    for (int rr = 0; rr < 4; ++rr) {
        float4 o = make_float4(acc[rr*4+0], acc[rr*4+1], acc[rr*4+2], acc[rr*4+3]);
        *(float4*)(O + (size_t)(ty * 4 + rr) * NDIM + tx * 4) = o;
    }
}

// ---------------------------------------------------------------------------
// Stage 3: LN_c(einsum) @ Wp + bp, * sg, * mask -> d_out
// grid (4096, 2), block 256, dyn smem 69632 B
// ---------------------------------------------------------------------------
__global__ void __launch_bounds__(256)
stage3_kernel(const float* __restrict__ mask,
              const float* __restrict__ ga2, const float* __restrict__ be2,
              const float* __restrict__ Wp,  const float* __restrict__ bp,
              float* __restrict__ out) {
    float* As = smem_;
    float* Bs = smem_ + 128 * 68;
    int tid = threadIdx.x;
    int tx = tid & 15, ty = tid >> 4;
    int rowbase = blockIdx.x * 64;
    int cbase   = blockIdx.y * 64;

    // gather channel-major einsum output + layernorm over channels
    {
        int r = tid >> 2, e = tid & 3;
        const float* base = g_ecm + (size_t)(e * 32) * PLANE + rowbase + r;
        float v[32];
        float s = 0.f, ss = 0.f;
        #pragma unroll
        for (int t = 0; t < 32; ++t) {
            float x = __ldg(base + (size_t)t * PLANE);
            v[t] = x; s += x; ss += x * x;
        }
        s  += __shfl_xor_sync(0xffffffffu, s, 1);
        s  += __shfl_xor_sync(0xffffffffu, s, 2);
        ss += __shfl_xor_sync(0xffffffffu, ss, 1);
        ss += __shfl_xor_sync(0xffffffffu, ss, 2);
        float mu = s * (1.0f / C);
        float rs = rsqrtf(ss * (1.0f / C) - mu * mu + 1e-5f);
        #pragma unroll
        for (int t = 0; t < 32; ++t) {
            int k = e * 32 + t;
            As[k * 68 + r] = (v[t] - mu) * rs * __ldg(ga2 + k) + __ldg(be2 + k);
        }
    }
    __syncthreads();

    load_w(Wp, cbase, Bs, tid);
    __syncthreads();
    float acc[16];
    #pragma unroll
    for (int t = 0; t < 16; ++t) acc[t] = 0.f;
    mm128(As, Bs, tx, ty, acc);

    #pragma unroll
    for (int rr = 0; rr < 4; ++rr) {
        int row = rowbase + ty * 4 + rr;
        int c0 = cbase + tx * 4;
        float m = __ldg(mask + row);
        float4 sgv = *(const float4*)(g_sg + (size_t)row * C + c0);
        float4 o;
        o.x = (acc[rr*4+0] + __ldg(bp + c0 + 0)) * sgv.x * m;
        o.y = (acc[rr*4+1] + __ldg(bp + c0 + 1)) * sgv.y * m;
        o.z = (acc[rr*4+2] + __ldg(bp + c0 + 2)) * sgv.z * m;
        o.w = (acc[rr*4+3] + __ldg(bp + c0 + 3)) * sgv.w * m;
        *(float4*)(out + (size_t)row * C + c0) = o;
    }
}

// ---------------------------------------------------------------------------
extern "C" void kernel_launch(void* const* d_in, const int* in_sizes, int n_in,
                              void* d_out, int out_size) {
    const float* x2d  = (const float*)d_in[0];
    const float* mask = (const float*)d_in[1];
    const float* ga1  = (const float*)d_in[2];
    const float* be1  = (const float*)d_in[3];
    const float* ga2  = (const float*)d_in[4];
    const float* be2  = (const float*)d_in[5];
    const float* Wi   = (const float*)d_in[6];
    const float* bi   = (const float*)d_in[7];
    const float* Wis  = (const float*)d_in[8];
    const float* bis  = (const float*)d_in[9];
    const float* Wj   = (const float*)d_in[10];
    const float* bj   = (const float*)d_in[11];
    const float* Wjs  = (const float*)d_in[12];
    const float* bjs  = (const float*)d_in[13];
    const float* Wp   = (const float*)d_in[14];
    const float* bp   = (const float*)d_in[15];
    const float* Ws   = (const float*)d_in[16];
    const float* bs   = (const float*)d_in[17];

    const int smem_big = 2 * 128 * 68 * (int)sizeof(float);   // 69632 B
    cudaFuncSetAttribute(stage1_kernel, cudaFuncAttributeMaxDynamicSharedMemorySize, smem_big);
    cudaFuncSetAttribute(stage3_kernel, cudaFuncAttributeMaxDynamicSharedMemorySize, smem_big);

    dim3 grid1(NN / 64, 2);
    stage1_kernel<<<grid1, 256, smem_big>>>(x2d, mask, ga1, be1,
                                            Wi, bi, Wis, bis,
                                            Wj, bj, Wjs, bjs,
                                            Ws, bs);

    dim3 grid2(NDIM / 64, NDIM / 64, C);
    einsum_kernel<<<grid2, 256>>>();

    stage3_kernel<<<grid1, 256, smem_big>>>(mask, ga2, be2, Wp, bp, (float*)d_out);
}

// round 3
// speedup vs baseline: 1.3193x; 1.3193x over previous
#include <cuda_runtime.h>
#include <cuda_bf16.h>
#include <cstdint>
#include <math.h>

#define NDIM 512
#define C 128
#define NN (NDIM*NDIM)        // 262144 flattened (i,k) positions
#define PLANE NN

// ---------------------------------------------------------------------------
// scratch (device globals; allocation forbidden in kernel_launch)
// bf16 planes, channel-major: plane c holds [row i][k] 512x512 bf16
// ---------------------------------------------------------------------------
__device__ __align__(16) __nv_bfloat16 g_ihi[(size_t)C*NN];
__device__ __align__(16) __nv_bfloat16 g_ilo[(size_t)C*NN];
__device__ __align__(16) __nv_bfloat16 g_jhi[(size_t)C*NN];
__device__ __align__(16) __nv_bfloat16 g_jlo[(size_t)C*NN];
__device__ __align__(16) float g_ecm[(size_t)C*NN];   // einsum out, channel-major
__device__ __align__(16) float g_sg [(size_t)NN*C];   // sigmoid(x@Ws+bs), row-major

extern __shared__ char smem_[];

// ---------------------------------------------------------------------------
// portable PTX helpers (compute_103-safe: ldmatrix / mma.sync / cp.async)
// ---------------------------------------------------------------------------
__device__ __forceinline__ uint32_t smem_u32(const void* p) {
    uint32_t a;
    asm("{ .reg .u64 t; cvta.to.shared.u64 t, %1; cvt.u32.u64 %0, t; }" : "=r"(a) : "l"(p));
    return a;
}
__device__ __forceinline__ void ldm_x4(uint32_t addr, uint32_t* r) {
    asm volatile("ldmatrix.sync.aligned.m8n8.x4.shared.b16 {%0,%1,%2,%3}, [%4];"
        : "=r"(r[0]), "=r"(r[1]), "=r"(r[2]), "=r"(r[3]) : "r"(addr));
}
__device__ __forceinline__ void mma_bf16(float* d, const uint32_t* a, uint32_t b0, uint32_t b1) {
    asm volatile("mma.sync.aligned.m16n8k16.row.col.f32.bf16.bf16.f32 "
        "{%0,%1,%2,%3}, {%4,%5,%6,%7}, {%8,%9}, {%0,%1,%2,%3};"
        : "+f"(d[0]), "+f"(d[1]), "+f"(d[2]), "+f"(d[3])
        : "r"(a[0]), "r"(a[1]), "r"(a[2]), "r"(a[3]), "r"(b0), "r"(b1));
}
__device__ __forceinline__ void cp16(uint32_t dst, const void* src) {
    asm volatile("cp.async.cg.shared.global [%0], [%1], 16;" :: "r"(dst), "l"(src) : "memory");
}
__device__ __forceinline__ float sigmoidf_(float x) { return 1.0f / (1.0f + __expf(-x)); }

__device__ __forceinline__ void split_bf16(float v, __nv_bfloat16& h, __nv_bfloat16& l) {
    h = __float2bfloat16_rn(v);
    l = __float2bfloat16_rn(v - __bfloat162float(h));
}

// ---------------------------------------------------------------------------
// warp GEMM over smem tiles, K=128, stride 136 bf16 (272 B) rows.
// A: [128 m][136] row-major (m,k). B: [128 n][136] (n,k). 8 warps: wm=w>>2 (2),
// wn=w&3 (4). Warp tile 64x32: 4 m-atoms x 4 n-atoms of m16n8k16.
// acc[(ma*4+na)*4 + q]: q=0:(g,2t) 1:(g,2t+1) 2:(g+8,2t) 3:(g+8,2t+1)
// ---------------------------------------------------------------------------
#define LDB2 272   // bytes per smem row (136 bf16)

__device__ __forceinline__ void wgemm128(uint32_t sAh, uint32_t sAl,
                                         uint32_t sBh, uint32_t sBl,
                                         int lane, int wm, int wn, float* acc) {
    int lr = lane & 7, sel = lane >> 3;
    uint32_t aRow = (uint32_t)((wm*64 + (sel & 1)*8 + lr) * LDB2 + (sel >> 1)*16);
    uint32_t bRow = (uint32_t)((wn*32 + (sel >> 1)*8 + lr) * LDB2 + (sel & 1)*16);
    #pragma unroll
    for (int kk = 0; kk < 8; ++kk) {
        uint32_t ah[4][4], al[4][4], bh[2][4], bl[2][4];
        #pragma unroll
        for (int ma = 0; ma < 4; ++ma) {
            uint32_t off = aRow + (uint32_t)(ma * 16 * LDB2 + kk * 32);
            ldm_x4(sAh + off, ah[ma]);
            ldm_x4(sAl + off, al[ma]);
        }
        #pragma unroll
        for (int p = 0; p < 2; ++p) {
            uint32_t off = bRow + (uint32_t)(p * 16 * LDB2 + kk * 32);
            ldm_x4(sBh + off, bh[p]);
            ldm_x4(sBl + off, bl[p]);
        }
        #pragma unroll
        for (int ma = 0; ma < 4; ++ma)
            #pragma unroll
            for (int na = 0; na < 4; ++na) {
                float* d = acc + (ma*4 + na)*4;
                int p = na >> 1, s = (na & 1) * 2;
                mma_bf16(d, ah[ma], bh[p][s], bh[p][s+1]);
                mma_bf16(d, ah[ma], bl[p][s], bl[p][s+1]);
                mma_bf16(d, al[ma], bh[p][s], bh[p][s+1]);
            }
    }
}

// load 128x128 fp32 weight W[k][n] -> smem transposed+split Wh/Wl[n][k]
__device__ __forceinline__ void loadWsplit(const float* __restrict__ W,
                                           __nv_bfloat16* Wh, __nv_bfloat16* Wl, int tid) {
    #pragma unroll
    for (int it = 0; it < 16; ++it) {
        int idx = tid + it * 256;
        int k = idx >> 5, n4 = (idx & 31) * 4;
        float4 w = *(const float4*)(W + k * C + n4);
        float v[4] = {w.x, w.y, w.z, w.w};
        #pragma unroll
        for (int j = 0; j < 4; ++j) {
            __nv_bfloat16 h, l;
            split_bf16(v[j], h, l);
            Wh[(n4 + j) * 136 + k] = h;
            Wl[(n4 + j) * 136 + k] = l;
        }
    }
}

// ---------------------------------------------------------------------------
// Stage 1: LN(x) + 5 GEMMs. grid 2048, block 256, dyn smem 139264 B
// ---------------------------------------------------------------------------
__global__ void __launch_bounds__(256, 1)
stage1_kernel(const float* __restrict__ x2d, const float* __restrict__ mask,
              const float* __restrict__ ga1, const float* __restrict__ be1,
              const float* __restrict__ Wi,  const float* __restrict__ bi,
              const float* __restrict__ Wis, const float* __restrict__ bis,
              const float* __restrict__ Wj,  const float* __restrict__ bj,
              const float* __restrict__ Wjs, const float* __restrict__ bjs,
              const float* __restrict__ Ws,  const float* __restrict__ bs) {
    __nv_bfloat16* Xh = (__nv_bfloat16*)smem_;
    __nv_bfloat16* Xl = Xh + 128 * 136;
    __nv_bfloat16* Wh = Xl + 128 * 136;
    __nv_bfloat16* Wl = Wh + 128 * 136;
    __nv_bfloat16* Th = Wh;   // transpose staging aliases W region
    __nv_bfloat16* Tl = Wl;
    uint32_t sXh = smem_u32(Xh), sXl = smem_u32(Xl);
    uint32_t sWh = smem_u32(Wh), sWl = smem_u32(Wl);

    int tid = threadIdx.x, lane = tid & 31, w = tid >> 5;
    int wm = w >> 2, wn = w & 3;
    int g = lane >> 2, t2 = (lane & 3) * 2;
    size_t rowbase = (size_t)blockIdx.x * 128;

    // ---- layernorm: 2 threads/row, 64 channels each ----
    {
        int r = tid >> 1, e = tid & 1;
        const float* xr = x2d + (rowbase + r) * C + e * 64;
        float v[64], s = 0.f, ss = 0.f;
        #pragma unroll
        for (int t = 0; t < 16; ++t) {
            float4 f = *(const float4*)(xr + t * 4);
            v[4*t+0]=f.x; v[4*t+1]=f.y; v[4*t+2]=f.z; v[4*t+3]=f.w;
            s += f.x + f.y + f.z + f.w;
            ss += f.x*f.x + f.y*f.y + f.z*f.z + f.w*f.w;
        }
        s  += __shfl_xor_sync(0xffffffffu, s, 1);
        ss += __shfl_xor_sync(0xffffffffu, ss, 1);
        float mu = s * (1.0f / C);
        float rs = rsqrtf(ss * (1.0f / C) - mu * mu + 1e-5f);
        #pragma unroll
        for (int t = 0; t < 64; ++t) {
            int k = e * 64 + t;
            float xn = (v[t] - mu) * rs * __ldg(ga1 + k) + __ldg(be1 + k);
            __nv_bfloat16 h, l;
            split_bf16(xn, h, l);
            Xh[r * 136 + k] = h;
            Xl[r * 136 + k] = l;
        }
    }
    __syncthreads();

    float accg[64], acc[64];

    #pragma unroll 1
    for (int pass = 0; pass < 2; ++pass) {
        const float* Wgp = pass ? Wjs : Wis;
        const float* bgp = pass ? bjs : bis;
        const float* Wmp = pass ? Wj  : Wi;
        const float* bmp = pass ? bj  : bi;
        __nv_bfloat16* outh = pass ? g_jhi : g_ihi;
        __nv_bfloat16* outl = pass ? g_jlo : g_ilo;

        // gate GEMM
        loadWsplit(Wgp, Wh, Wl, tid);
        __syncthreads();
        #pragma unroll
        for (int q = 0; q < 64; ++q) accg[q] = 0.f;
        wgemm128(sXh, sXl, sWh, sWl, lane, wm, wn, accg);
        #pragma unroll
        for (int ma = 0; ma < 4; ++ma)
            #pragma unroll
            for (int na = 0; na < 4; ++na) {
                int idx = (ma*4 + na) * 4;
                int c0 = wn*32 + na*8 + t2;
                accg[idx+0] = sigmoidf_(accg[idx+0] + __ldg(bgp + c0));
                accg[idx+1] = sigmoidf_(accg[idx+1] + __ldg(bgp + c0 + 1));
                accg[idx+2] = sigmoidf_(accg[idx+2] + __ldg(bgp + c0));
                accg[idx+3] = sigmoidf_(accg[idx+3] + __ldg(bgp + c0 + 1));
            }
        __syncthreads();

        // main GEMM
        loadWsplit(Wmp, Wh, Wl, tid);
        __syncthreads();
        #pragma unroll
        for (int q = 0; q < 64; ++q) acc[q] = 0.f;
        wgemm128(sXh, sXl, sWh, sWl, lane, wm, wn, acc);
        __syncthreads();   // done reading W before T overwrite

        // combine -> transpose staging T[col][row]
        #pragma unroll
        for (int ma = 0; ma < 4; ++ma) {
            int r0 = wm*64 + ma*16 + g;
            float m0 = __ldg(mask + rowbase + r0);
            float m1 = __ldg(mask + rowbase + r0 + 8);
            #pragma unroll
            for (int na = 0; na < 4; ++na) {
                int idx = (ma*4 + na) * 4;
                int c0 = wn*32 + na*8 + t2;
                float b0 = __ldg(bmp + c0), b1 = __ldg(bmp + c0 + 1);
                float v0 = (acc[idx+0] + b0) * accg[idx+0] * m0;
                float v1 = (acc[idx+1] + b1) * accg[idx+1] * m0;
                float v2 = (acc[idx+2] + b0) * accg[idx+2] * m1;
                float v3 = (acc[idx+3] + b1) * accg[idx+3] * m1;
                __nv_bfloat16 h, l;
                split_bf16(v0, h, l); Th[(c0  )*136 + r0    ] = h; Tl[(c0  )*136 + r0    ] = l;
                split_bf16(v1, h, l); Th[(c0+1)*136 + r0    ] = h; Tl[(c0+1)*136 + r0    ] = l;
                split_bf16(v2, h, l); Th[(c0  )*136 + r0 + 8] = h; Tl[(c0  )*136 + r0 + 8] = l;
                split_bf16(v3, h, l); Th[(c0+1)*136 + r0 + 8] = h; Tl[(c0+1)*136 + r0 + 8] = l;
            }
        }
        __syncthreads();

        // channel-major flush
        {
            int cch = tid >> 1, half = tid & 1;
            const uint4* srcH = (const uint4*)(Th + cch * 136 + half * 64);
            const uint4* srcL = (const uint4*)(Tl + cch * 136 + half * 64);
            uint4* dstH = (uint4*)(outh + (size_t)cch * PLANE + rowbase + half * 64);
            uint4* dstL = (uint4*)(outl + (size_t)cch * PLANE + rowbase + half * 64);
            #pragma unroll
            for (int q = 0; q < 8; ++q) { dstH[q] = srcH[q]; dstL[q] = srcL[q]; }
        }
        __syncthreads();
    }

    // sg = sigmoid(x@Ws+bs), row-major fp32
    loadWsplit(Ws, Wh, Wl, tid);
    __syncthreads();
    #pragma unroll
    for (int q = 0; q < 64; ++q) acc[q] = 0.f;
    wgemm128(sXh, sXl, sWh, sWl, lane, wm, wn, acc);
    #pragma unroll
    for (int ma = 0; ma < 4; ++ma) {
        size_t r0 = rowbase + wm*64 + ma*16 + g;
        #pragma unroll
        for (int na = 0; na < 4; ++na) {
            int idx = (ma*4 + na) * 4;
            int c0 = wn*32 + na*8 + t2;
            float b0 = __ldg(bs + c0), b1 = __ldg(bs + c0 + 1);
            float2 p0 = make_float2(sigmoidf_(acc[idx+0] + b0), sigmoidf_(acc[idx+1] + b1));
            float2 p1 = make_float2(sigmoidf_(acc[idx+2] + b0), sigmoidf_(acc[idx+3] + b1));
            *(float2*)(g_sg + r0 * C + c0) = p0;
            *(float2*)(g_sg + (r0 + 8) * C + c0) = p1;
        }
    }
}

// ---------------------------------------------------------------------------
// Stage 2: einsum O_c = I_c @ J_c^T per channel via mma.sync + cp.async
// grid (4,4,128), block 256, dyn smem 81920 B
// tiles stride 40 bf16 (80 B): conflict-free ldmatrix
// ---------------------------------------------------------------------------
#define EBUF 10240          // 128 rows x 80 B
#define ECH  (4 * EBUF)     // Ah, Al, Bh, Bl

__device__ __forceinline__ void e_load(uint32_t sdst,
                                       const char* pAh, const char* pAl,
                                       const char* pBh, const char* pBl,
                                       int kb, int tid) {
    #pragma unroll
    for (int it = 0; it < 8; ++it) {
        int idx = tid + it * 256;
        int tile = idx >> 9;
        int rem = idx & 511;
        int row = rem >> 2, ch = rem & 3;
        const char* src = (tile == 0) ? pAh : (tile == 1) ? pAl : (tile == 2) ? pBh : pBl;
        size_t goff = (size_t)row * 1024 + (size_t)kb * 64 + ch * 16;
        cp16(sdst + tile * EBUF + row * 80 + ch * 16, src + goff);
    }
}

__device__ __forceinline__ void e_mma(uint32_t base, int lane, int wm, int wn, float* acc) {
    int lr = lane & 7, sel = lane >> 3;
    uint32_t aRow = (uint32_t)((wm*64 + (sel & 1)*8 + lr) * 80 + (sel >> 1)*16);
    uint32_t bRow = (uint32_t)((wn*32 + (sel >> 1)*8 + lr) * 80 + (sel & 1)*16);
    uint32_t sAh = base, sAl = base + EBUF, sBh = base + 2*EBUF, sBl = base + 3*EBUF;
    #pragma unroll
    for (int kk = 0; kk < 2; ++kk) {
        uint32_t ah[4][4], al[4][4], bh[2][4], bl[2][4];
        #pragma unroll
        for (int ma = 0; ma < 4; ++ma) {
            uint32_t off = aRow + (uint32_t)(ma * 16 * 80 + kk * 32);
            ldm_x4(sAh + off, ah[ma]);
            ldm_x4(sAl + off, al[ma]);
        }
        #pragma unroll
        for (int p = 0; p < 2; ++p) {
            uint32_t off = bRow + (uint32_t)(p * 16 * 80 + kk * 32);
            ldm_x4(sBh + off, bh[p]);
            ldm_x4(sBl + off, bl[p]);
        }
        #pragma unroll
        for (int ma = 0; ma < 4; ++ma)
            #pragma unroll
            for (int na = 0; na < 4; ++na) {
                float* d = acc + (ma*4 + na)*4;
                int p = na >> 1, s = (na & 1) * 2;
                mma_bf16(d, ah[ma], bh[p][s], bh[p][s+1]);
                mma_bf16(d, ah[ma], bl[p][s], bl[p][s+1]);
                mma_bf16(d, al[ma], bh[p][s], bh[p][s+1]);
            }
    }
}

__global__ void __launch_bounds__(256, 1)
einsum_kernel() {
    uint32_t sb = smem_u32(smem_);
    int tid = threadIdx.x, lane = tid & 31, w = tid >> 5;
    int wm = w >> 2, wn = w & 3;
    int g = lane >> 2, t2 = (lane & 3) * 2;
    int c = blockIdx.z;
    int ibase = blockIdx.x * 128, jbase = blockIdx.y * 128;

    size_t cpl = (size_t)c * PLANE * 2;      // plane byte offset
    const char* pAh = (const char*)g_ihi + cpl + (size_t)ibase * 1024;
    const char* pAl = (const char*)g_ilo + cpl + (size_t)ibase * 1024;
    const char* pBh = (const char*)g_jhi + cpl + (size_t)jbase * 1024;
    const char* pBl = (const char*)g_jlo + cpl + (size_t)jbase * 1024;

    float acc[64];
    #pragma unroll
    for (int q = 0; q < 64; ++q) acc[q] = 0.f;

    e_load(sb, pAh, pAl, pBh, pBl, 0, tid);
    asm volatile("cp.async.commit_group;" ::: "memory");

    for (int kb = 0; kb < 16; ++kb) {
        if (kb < 15) {
            e_load(sb + ((kb + 1) & 1) * ECH, pAh, pAl, pBh, pBl, kb + 1, tid);
            asm volatile("cp.async.commit_group;" ::: "memory");
            asm volatile("cp.async.wait_group 1;" ::: "memory");
        } else {
            asm volatile("cp.async.wait_group 0;" ::: "memory");
        }
        __syncthreads();
        e_mma(sb + (kb & 1) * ECH, lane, wm, wn, acc);
        __syncthreads();
    }

    float* O = g_ecm + (size_t)c * PLANE;
    #pragma unroll
    for (int ma = 0; ma < 4; ++ma) {
        size_t r0 = (size_t)(ibase + wm*64 + ma*16 + g);
        #pragma unroll
        for (int na = 0; na < 4; ++na) {
            int idx = (ma*4 + na) * 4;
            int c0 = jbase + wn*32 + na*8 + t2;
            *(float2*)(O + r0 * NDIM + c0)       = make_float2(acc[idx+0], acc[idx+1]);
            *(float2*)(O + (r0 + 8) * NDIM + c0) = make_float2(acc[idx+2], acc[idx+3]);
        }
    }
}

// ---------------------------------------------------------------------------
// Stage 3: LN_c(einsum) @ Wp + bp, * sg, * mask -> out
// grid 2048, block 256, dyn smem 139264 B
// ---------------------------------------------------------------------------
__global__ void __launch_bounds__(256, 1)
stage3_kernel(const float* __restrict__ mask,
              const float* __restrict__ ga2, const float* __restrict__ be2,
              const float* __restrict__ Wp,  const float* __restrict__ bp,
              float* __restrict__ out) {
    __nv_bfloat16* Ah = (__nv_bfloat16*)smem_;
    __nv_bfloat16* Al = Ah + 128 * 136;
    __nv_bfloat16* Wh = Al + 128 * 136;
    __nv_bfloat16* Wl = Wh + 128 * 136;
    uint32_t sAh = smem_u32(Ah), sAl = smem_u32(Al);
    uint32_t sWh = smem_u32(Wh), sWl = smem_u32(Wl);

    int tid = threadIdx.x, lane = tid & 31, w = tid >> 5;
    int wm = w >> 2, wn = w & 3;
    int g = lane >> 2, t2 = (lane & 3) * 2;
    size_t rowbase = (size_t)blockIdx.x * 128;

    // gather channel-major einsum output + LN over channels
    {
        int r = tid >> 1, e = tid & 1;
        const float* base = g_ecm + (size_t)(e * 64) * PLANE + rowbase + r;
        float v[64], s = 0.f, ss = 0.f;
        #pragma unroll
        for (int t = 0; t < 64; ++t) {
            float x = __ldg(base + (size_t)t * PLANE);
            v[t] = x; s += x; ss += x * x;
        }
        s  += __shfl_xor_sync(0xffffffffu, s, 1);
        ss += __shfl_xor_sync(0xffffffffu, ss, 1);
        float mu = s * (1.0f / C);
        float rs = rsqrtf(ss * (1.0f / C) - mu * mu + 1e-5f);
        #pragma unroll
        for (int t = 0; t < 64; ++t) {
            int k = e * 64 + t;
            float xn = (v[t] - mu) * rs * __ldg(ga2 + k) + __ldg(be2 + k);
            __nv_bfloat16 h, l;
            split_bf16(xn, h, l);
            Ah[r * 136 + k] = h;
            Al[r * 136 + k] = l;
        }
    }
    loadWsplit(Wp, Wh, Wl, tid);
    __syncthreads();

    float acc[64];
    #pragma unroll
    for (int q = 0; q < 64; ++q) acc[q] = 0.f;
    wgemm128(sAh, sAl, sWh, sWl, lane, wm, wn, acc);

    #pragma unroll
    for (int ma = 0; ma < 4; ++ma) {
        size_t r0 = rowbase + wm*64 + ma*16 + g;
        float m0 = __ldg(mask + r0);
        float m1 = __ldg(mask + r0 + 8);
        #pragma unroll
        for (int na = 0; na < 4; ++na) {
            int idx = (ma*4 + na) * 4;
            int c0 = wn*32 + na*8 + t2;
            float b0 = __ldg(bp + c0), b1 = __ldg(bp + c0 + 1);
            float2 s0 = *(const float2*)(g_sg + r0 * C + c0);
            float2 s1 = *(const float2*)(g_sg + (r0 + 8) * C + c0);
            *(float2*)(out + r0 * C + c0) =
                make_float2((acc[idx+0] + b0) * s0.x * m0, (acc[idx+1] + b1) * s0.y * m0);
            *(float2*)(out + (r0 + 8) * C + c0) =
                make_float2((acc[idx+2] + b0) * s1.x * m1, (acc[idx+3] + b1) * s1.y * m1);
        }
    }
}

// ---------------------------------------------------------------------------
extern "C" void kernel_launch(void* const* d_in, const int* in_sizes, int n_in,
                              void* d_out, int out_size) {
    const float* x2d  = (const float*)d_in[0];
    const float* mask = (const float*)d_in[1];
    const float* ga1  = (const float*)d_in[2];
    const float* be1  = (const float*)d_in[3];
    const float* ga2  = (const float*)d_in[4];
    const float* be2  = (const float*)d_in[5];
    const float* Wi   = (const float*)d_in[6];
    const float* bi   = (const float*)d_in[7];
    const float* Wis  = (const float*)d_in[8];
    const float* bis  = (const float*)d_in[9];
    const float* Wj   = (const float*)d_in[10];
    const float* bj   = (const float*)d_in[11];
    const float* Wjs  = (const float*)d_in[12];
    const float* bjs  = (const float*)d_in[13];
    const float* Wp   = (const float*)d_in[14];
    const float* bp   = (const float*)d_in[15];
    const float* Ws   = (const float*)d_in[16];
    const float* bs   = (const float*)d_in[17];

    const int smem_big = 4 * 128 * 136 * 2;   // 139264 B
    const int smem_ein = 2 * ECH;             // 81920 B
    cudaFuncSetAttribute(stage1_kernel, cudaFuncAttributeMaxDynamicSharedMemorySize, smem_big);
    cudaFuncSetAttribute(stage3_kernel, cudaFuncAttributeMaxDynamicSharedMemorySize, smem_big);
    cudaFuncSetAttribute(einsum_kernel, cudaFuncAttributeMaxDynamicSharedMemorySize, smem_ein);

    stage1_kernel<<<NN / 128, 256, smem_big>>>(x2d, mask, ga1, be1,
                                               Wi, bi, Wis, bis,
                                               Wj, bj, Wjs, bjs,
                                               Ws, bs);

    dim3 grid2(NDIM / 128, NDIM / 128, C);
    einsum_kernel<<<grid2, 256, smem_ein>>>();

    stage3_kernel<<<NN / 128, 256, smem_big>>>(mask, ga2, be2, Wp, bp, (float*)d_out);
}

// round 4
// speedup vs baseline: 2.2435x; 1.7006x over previous
#include <cuda_runtime.h>
#include <cuda_bf16.h>
#include <cstdint>
#include <math.h>

#define NDIM 512
#define C 128
#define NN (NDIM*NDIM)
#define PLANE NN
#define WSZ 17408          // bf16 elements per smem weight/X array (128 x 136)
#define WSZB 34816         // bytes

// ---------------------------------------------------------------------------
// scratch
// ---------------------------------------------------------------------------
__device__ __align__(16) __nv_bfloat16 g_ihi[(size_t)C*NN];
__device__ __align__(16) __nv_bfloat16 g_ilo[(size_t)C*NN];
__device__ __align__(16) __nv_bfloat16 g_jhi[(size_t)C*NN];
__device__ __align__(16) __nv_bfloat16 g_jlo[(size_t)C*NN];
__device__ __align__(16) float g_ecm[(size_t)C*NN];
__device__ __align__(16) float g_sg [(size_t)NN*C];
// pre-split weights: [m][hi/lo][n][k], m: 0=Wis 1=Wi 2=Wjs 3=Wj 4=Ws 5=Wp
__device__ __align__(16) __nv_bfloat16 g_wq[6 * 2 * 128 * 128];

extern __shared__ char smem_[];

// ---------------------------------------------------------------------------
// portable PTX helpers
// ---------------------------------------------------------------------------
__device__ __forceinline__ uint32_t smem_u32(const void* p) {
    uint32_t a;
    asm("{ .reg .u64 t; cvta.to.shared.u64 t, %1; cvt.u32.u64 %0, t; }" : "=r"(a) : "l"(p));
    return a;
}
__device__ __forceinline__ void ldm_x4(uint32_t addr, uint32_t* r) {
    asm volatile("ldmatrix.sync.aligned.m8n8.x4.shared.b16 {%0,%1,%2,%3}, [%4];"
        : "=r"(r[0]), "=r"(r[1]), "=r"(r[2]), "=r"(r[3]) : "r"(addr));
}
__device__ __forceinline__ void mma_bf16(float* d, const uint32_t* a, uint32_t b0, uint32_t b1) {
    asm volatile("mma.sync.aligned.m16n8k16.row.col.f32.bf16.bf16.f32 "
        "{%0,%1,%2,%3}, {%4,%5,%6,%7}, {%8,%9}, {%0,%1,%2,%3};"
        : "+f"(d[0]), "+f"(d[1]), "+f"(d[2]), "+f"(d[3])
        : "r"(a[0]), "r"(a[1]), "r"(a[2]), "r"(a[3]), "r"(b0), "r"(b1));
}
__device__ __forceinline__ void cp16(uint32_t dst, const void* src) {
    asm volatile("cp.async.cg.shared.global [%0], [%1], 16;" :: "r"(dst), "l"(src) : "memory");
}
#define CP_COMMIT() asm volatile("cp.async.commit_group;" ::: "memory")
#define CP_WAIT(n)  asm volatile("cp.async.wait_group %0;" :: "n"(n) : "memory")
__device__ __forceinline__ float sigmoidf_(float x) { return 1.0f / (1.0f + __expf(-x)); }
__device__ __forceinline__ void split_bf16(float v, __nv_bfloat16& h, __nv_bfloat16& l) {
    h = __float2bfloat16_rn(v);
    l = __float2bfloat16_rn(v - __bfloat162float(h));
}

// ---------------------------------------------------------------------------
// Prologue: split+transpose 6 weights into g_wq. grid 6, block 256
// ---------------------------------------------------------------------------
__global__ void convert_w_kernel(const float* __restrict__ Wis, const float* __restrict__ Wi,
                                 const float* __restrict__ Wjs, const float* __restrict__ Wj,
                                 const float* __restrict__ Ws,  const float* __restrict__ Wp) {
    const float* src[6] = {Wis, Wi, Wjs, Wj, Ws, Wp};
    const float* W = src[blockIdx.x];
    __nv_bfloat16* outh = g_wq + (size_t)blockIdx.x * 32768;
    __nv_bfloat16* outl = outh + 16384;
    for (int idx = threadIdx.x; idx < 16384; idx += blockDim.x) {
        int n = idx >> 7, k = idx & 127;
        float v = W[k * 128 + n];
        __nv_bfloat16 h, l;
        split_bf16(v, h, l);
        outh[n * 128 + k] = h;
        outl[n * 128 + k] = l;
    }
}

// cp.async one pre-split weight pair into smem (hi at sW, lo at sW+WSZB), 512 thr
__device__ __forceinline__ void loadWq(int m, uint32_t sW, int tid) {
    const char* src = (const char*)g_wq + (size_t)m * 65536;
    #pragma unroll
    for (int it = 0; it < 8; ++it) {
        int idx = tid + it * 512;
        int arr = idx >> 11, rem = idx & 2047;
        int row = rem >> 4, ch = rem & 15;
        cp16(sW + arr * WSZB + row * 272 + ch * 16,
             src + arr * 32768 + row * 256 + ch * 16);
    }
}

// ---------------------------------------------------------------------------
// 16-warp GEMM: A[128][k128] @ B[128][k128]^T, warp tile 32x32
// sA/sB point at hi arrays (stride 272 B); lo at +WSZB. acc[32].
// wm = w>>2 rows, wn = w&3 cols. ma 2 atoms m16, na 4 atoms n8, 3-term split.
// acc[(ma*4+na)*4+q]: q=0:(g,t2) 1:(g,t2+1) 2:(g+8,t2) 3:(g+8,t2+1)
// ---------------------------------------------------------------------------
__device__ __forceinline__ void wgemm16(uint32_t sA, uint32_t sB,
                                        int lane, int wm, int wn, float* acc) {
    int lr = lane & 7, sel = lane >> 3;
    uint32_t aRow = (uint32_t)((wm*32 + (sel & 1)*8 + lr) * 272 + (sel >> 1)*16);
    uint32_t bRow = (uint32_t)((wn*32 + (sel >> 1)*8 + lr) * 272 + (sel & 1)*16);
    #pragma unroll
    for (int kk = 0; kk < 8; ++kk) {
        uint32_t ah[2][4], al[2][4];
        #pragma unroll
        for (int ma = 0; ma < 2; ++ma) {
            uint32_t off = aRow + (uint32_t)(ma * 16 * 272 + kk * 32);
            ldm_x4(sA + off, ah[ma]);
            ldm_x4(sA + WSZB + off, al[ma]);
        }
        #pragma unroll
        for (int p = 0; p < 2; ++p) {
            uint32_t bh[4], bl[4];
            uint32_t off = bRow + (uint32_t)(p * 16 * 272 + kk * 32);
            ldm_x4(sB + off, bh);
            ldm_x4(sB + WSZB + off, bl);
            #pragma unroll
            for (int ma = 0; ma < 2; ++ma)
                #pragma unroll
                for (int h = 0; h < 2; ++h) {
                    float* d = acc + (ma*4 + p*2 + h)*4;
                    int s = h * 2;
                    mma_bf16(d, ah[ma], bh[s], bh[s+1]);
                    mma_bf16(d, ah[ma], bl[s], bl[s+1]);
                    mma_bf16(d, al[ma], bh[s], bh[s+1]);
                }
        }
    }
}

// ---------------------------------------------------------------------------
// Stage 1: LN(x) + 5 GEMMs, 512 threads, double-buffered weight pipeline
// smem: Xh Xl | W0h W0l | W1h W1l  = 6*34816 = 208896 B
// ---------------------------------------------------------------------------
__global__ void __launch_bounds__(512, 1)
stage1_kernel(const float* __restrict__ x2d, const float* __restrict__ mask,
              const float* __restrict__ ga1, const float* __restrict__ be1,
              const float* __restrict__ bi,  const float* __restrict__ bis,
              const float* __restrict__ bj,  const float* __restrict__ bjs,
              const float* __restrict__ bs) {
    __nv_bfloat16* Xh = (__nv_bfloat16*)smem_;
    __nv_bfloat16* T0 = Xh + 2 * WSZ;   // W0 (hi,lo)
    __nv_bfloat16* T1 = Xh + 4 * WSZ;   // W1 (hi,lo) / transpose staging
    uint32_t sX  = smem_u32(Xh);
    uint32_t sW0 = sX + 2 * WSZB;
    uint32_t sW1 = sX + 4 * WSZB;

    int tid = threadIdx.x, lane = tid & 31, w = tid >> 5;
    int wm = w >> 2, wn = w & 3;
    int g = lane >> 2, t2 = (lane & 3) * 2;
    size_t rowbase = (size_t)blockIdx.x * 128;

    // prefetch gate+main weights of pass 0
    loadWq(0, sW0, tid); CP_COMMIT();
    loadWq(1, sW1, tid); CP_COMMIT();

    // ---- layernorm: 4 threads/row, 32 channels each ----
    {
        int r = tid >> 2, e = tid & 3;
        const float* xr = x2d + (rowbase + r) * C + e * 32;
        float v[32], s = 0.f, ss = 0.f;
        #pragma unroll
        for (int t = 0; t < 8; ++t) {
            float4 f = *(const float4*)(xr + t * 4);
            v[4*t+0]=f.x; v[4*t+1]=f.y; v[4*t+2]=f.z; v[4*t+3]=f.w;
            s += f.x + f.y + f.z + f.w;
            ss += f.x*f.x + f.y*f.y + f.z*f.z + f.w*f.w;
        }
        s  += __shfl_xor_sync(0xffffffffu, s, 1);
        s  += __shfl_xor_sync(0xffffffffu, s, 2);
        ss += __shfl_xor_sync(0xffffffffu, ss, 1);
        ss += __shfl_xor_sync(0xffffffffu, ss, 2);
        float mu = s * (1.0f / C);
        float rs = rsqrtf(ss * (1.0f / C) - mu * mu + 1e-5f);
        #pragma unroll
        for (int t = 0; t < 32; ++t) {
            int k = e * 32 + t;
            float xn = (v[t] - mu) * rs * __ldg(ga1 + k) + __ldg(be1 + k);
            __nv_bfloat16 h, l;
            split_bf16(xn, h, l);
            Xh[r * 136 + k] = h;
            Xh[WSZ + r * 136 + k] = l;
        }
    }

    float accg[32], acc[32];

    #pragma unroll 1
    for (int pass = 0; pass < 2; ++pass) {
        const float* bgp = pass ? bjs : bis;
        const float* bmp = pass ? bj  : bi;
        __nv_bfloat16* outh = pass ? g_jhi : g_ihi;
        __nv_bfloat16* outl = pass ? g_jlo : g_ilo;

        // ---- gate GEMM from W0 ----
        CP_WAIT(1);
        __syncthreads();
        #pragma unroll
        for (int q = 0; q < 32; ++q) accg[q] = 0.f;
        wgemm16(sX, sW0, lane, wm, wn, accg);
        #pragma unroll
        for (int ma = 0; ma < 2; ++ma)
            #pragma unroll
            for (int na = 0; na < 4; ++na) {
                int idx = (ma*4 + na) * 4;
                int c0 = wn*32 + na*8 + t2;
                float b0 = __ldg(bgp + c0), b1 = __ldg(bgp + c0 + 1);
                accg[idx+0] = sigmoidf_(accg[idx+0] + b0);
                accg[idx+1] = sigmoidf_(accg[idx+1] + b1);
                accg[idx+2] = sigmoidf_(accg[idx+2] + b0);
                accg[idx+3] = sigmoidf_(accg[idx+3] + b1);
            }
        __syncthreads();                 // done reading W0
        loadWq(pass ? 4 : 2, sW0, tid);  // next gate (or Ws) -> W0
        CP_COMMIT();

        // ---- main GEMM from W1 ----
        CP_WAIT(1);
        __syncthreads();
        #pragma unroll
        for (int q = 0; q < 32; ++q) acc[q] = 0.f;
        wgemm16(sX, sW1, lane, wm, wn, acc);
        __syncthreads();                 // done reading W1 -> reuse as staging

        // combine -> transpose staging T1[col][row]
        #pragma unroll
        for (int ma = 0; ma < 2; ++ma) {
            int r0 = wm*32 + ma*16 + g;
            float m0 = __ldg(mask + rowbase + r0);
            float m1 = __ldg(mask + rowbase + r0 + 8);
            #pragma unroll
            for (int na = 0; na < 4; ++na) {
                int idx = (ma*4 + na) * 4;
                int c0 = wn*32 + na*8 + t2;
                float b0 = __ldg(bmp + c0), b1 = __ldg(bmp + c0 + 1);
                float v0 = (acc[idx+0] + b0) * accg[idx+0] * m0;
                float v1 = (acc[idx+1] + b1) * accg[idx+1] * m0;
                float v2 = (acc[idx+2] + b0) * accg[idx+2] * m1;
                float v3 = (acc[idx+3] + b1) * accg[idx+3] * m1;
                __nv_bfloat16 h, l;
                split_bf16(v0, h, l); T1[(c0  )*136 + r0    ] = h; T1[WSZ + (c0  )*136 + r0    ] = l;
                split_bf16(v1, h, l); T1[(c0+1)*136 + r0    ] = h; T1[WSZ + (c0+1)*136 + r0    ] = l;
                split_bf16(v2, h, l); T1[(c0  )*136 + r0 + 8] = h; T1[WSZ + (c0  )*136 + r0 + 8] = l;
                split_bf16(v3, h, l); T1[(c0+1)*136 + r0 + 8] = h; T1[WSZ + (c0+1)*136 + r0 + 8] = l;
            }
        }
        __syncthreads();

        // channel-major flush: thread -> 32 rows (64 B) of one channel
        {
            int cch = tid >> 2, q = tid & 3;
            const uint4* srcH = (const uint4*)(T1 + cch * 136 + q * 32);
            const uint4* srcL = (const uint4*)(T1 + WSZ + cch * 136 + q * 32);
            uint4* dstH = (uint4*)(outh + (size_t)cch * PLANE + rowbase + q * 32);
            uint4* dstL = (uint4*)(outl + (size_t)cch * PLANE + rowbase + q * 32);
            #pragma unroll
            for (int t = 0; t < 4; ++t) { dstH[t] = srcH[t]; dstL[t] = srcL[t]; }
        }
        __syncthreads();                 // staging consumed
        if (pass == 0) { loadWq(3, sW1, tid); CP_COMMIT(); }   // Wj -> W1
    }

    // ---- sg = sigmoid(x@Ws+bs) from W0 ----
    CP_WAIT(0);
    __syncthreads();
    #pragma unroll
    for (int q = 0; q < 32; ++q) acc[q] = 0.f;
    wgemm16(sX, sW0, lane, wm, wn, acc);
    #pragma unroll
    for (int ma = 0; ma < 2; ++ma) {
        size_t r0 = rowbase + wm*32 + ma*16 + g;
        #pragma unroll
        for (int na = 0; na < 4; ++na) {
            int idx = (ma*4 + na) * 4;
            int c0 = wn*32 + na*8 + t2;
            float b0 = __ldg(bs + c0), b1 = __ldg(bs + c0 + 1);
            *(float2*)(g_sg + r0 * C + c0) =
                make_float2(sigmoidf_(acc[idx+0] + b0), sigmoidf_(acc[idx+1] + b1));
            *(float2*)(g_sg + (r0 + 8) * C + c0) =
                make_float2(sigmoidf_(acc[idx+2] + b0), sigmoidf_(acc[idx+3] + b1));
        }
    }
}

// ---------------------------------------------------------------------------
// Stage 2: einsum O_c = I_c @ J_c^T, mma.sync + cp.async, 2 CTAs/SM
// grid (4,4,128), block 256, dyn smem 81920 B
// ---------------------------------------------------------------------------
#define EBUF 10240
#define ECH  (4 * EBUF)

__device__ __forceinline__ void e_load(uint32_t sdst,
                                       const char* pAh, const char* pAl,
                                       const char* pBh, const char* pBl,
                                       int kb, int tid) {
    #pragma unroll
    for (int it = 0; it < 8; ++it) {
        int idx = tid + it * 256;
        int tile = idx >> 9;
        int rem = idx & 511;
        int row = rem >> 2, ch = rem & 3;
        const char* src = (tile == 0) ? pAh : (tile == 1) ? pAl : (tile == 2) ? pBh : pBl;
        size_t goff = (size_t)row * 1024 + (size_t)kb * 64 + ch * 16;
        cp16(sdst + tile * EBUF + row * 80 + ch * 16, src + goff);
    }
}

__device__ __forceinline__ void e_mma(uint32_t base, int lane, int wm, int wn, float* acc) {
    int lr = lane & 7, sel = lane >> 3;
    uint32_t aRow = (uint32_t)((wm*64 + (sel & 1)*8 + lr) * 80 + (sel >> 1)*16);
    uint32_t bRow = (uint32_t)((wn*32 + (sel >> 1)*8 + lr) * 80 + (sel & 1)*16);
    uint32_t sAh = base, sAl = base + EBUF, sBh = base + 2*EBUF, sBl = base + 3*EBUF;
    #pragma unroll
    for (int kk = 0; kk < 2; ++kk) {
        uint32_t ah[4][4], al[4][4];
        #pragma unroll
        for (int ma = 0; ma < 4; ++ma) {
            uint32_t off = aRow + (uint32_t)(ma * 16 * 80 + kk * 32);
            ldm_x4(sAh + off, ah[ma]);
            ldm_x4(sAl + off, al[ma]);
        }
        #pragma unroll
        for (int p = 0; p < 2; ++p) {
            uint32_t bh[4], bl[4];
            uint32_t off = bRow + (uint32_t)(p * 16 * 80 + kk * 32);
            ldm_x4(sBh + off, bh);
            ldm_x4(sBl + off, bl);
            #pragma unroll
            for (int ma = 0; ma < 4; ++ma)
                #pragma unroll
                for (int h = 0; h < 2; ++h) {
                    float* d = acc + (ma*4 + p*2 + h)*4;
                    int s = h * 2;
                    mma_bf16(d, ah[ma], bh[s], bh[s+1]);
                    mma_bf16(d, ah[ma], bl[s], bl[s+1]);
                    mma_bf16(d, al[ma], bh[s], bh[s+1]);
                }
        }
    }
}

__global__ void __launch_bounds__(256, 2)
einsum_kernel() {
    uint32_t sb = smem_u32(smem_);
    int tid = threadIdx.x, lane = tid & 31, w = tid >> 5;
    int wm = w >> 2, wn = w & 3;
    int g = lane >> 2, t2 = (lane & 3) * 2;
    int c = blockIdx.z;
    int ibase = blockIdx.x * 128, jbase = blockIdx.y * 128;

    size_t cpl = (size_t)c * PLANE * 2;
    const char* pAh = (const char*)g_ihi + cpl + (size_t)ibase * 1024;
    const char* pAl = (const char*)g_ilo + cpl + (size_t)ibase * 1024;
    const char* pBh = (const char*)g_jhi + cpl + (size_t)jbase * 1024;
    const char* pBl = (const char*)g_jlo + cpl + (size_t)jbase * 1024;

    float acc[64];
    #pragma unroll
    for (int q = 0; q < 64; ++q) acc[q] = 0.f;

    e_load(sb, pAh, pAl, pBh, pBl, 0, tid);
    CP_COMMIT();

    for (int kb = 0; kb < 16; ++kb) {
        if (kb < 15) {
            e_load(sb + ((kb + 1) & 1) * ECH, pAh, pAl, pBh, pBl, kb + 1, tid);
            CP_COMMIT();
            CP_WAIT(1);
        } else {
            CP_WAIT(0);
        }
        __syncthreads();
        e_mma(sb + (kb & 1) * ECH, lane, wm, wn, acc);
        __syncthreads();
    }

    float* O = g_ecm + (size_t)c * PLANE;
    #pragma unroll
    for (int ma = 0; ma < 4; ++ma) {
        size_t r0 = (size_t)(ibase + wm*64 + ma*16 + g);
        #pragma unroll
        for (int na = 0; na < 4; ++na) {
            int idx = (ma*4 + na) * 4;
            int c0 = jbase + wn*32 + na*8 + t2;
            *(float2*)(O + r0 * NDIM + c0)       = make_float2(acc[idx+0], acc[idx+1]);
            *(float2*)(O + (r0 + 8) * NDIM + c0) = make_float2(acc[idx+2], acc[idx+3]);
        }
    }
}

// ---------------------------------------------------------------------------
// Stage 3: LN_c(einsum) @ Wp + bp, * sg, * mask -> out. 512 threads.
// smem: Xh Xl | Wh Wl = 139264 B
// ---------------------------------------------------------------------------
__global__ void __launch_bounds__(512, 1)
stage3_kernel(const float* __restrict__ mask,
              const float* __restrict__ ga2, const float* __restrict__ be2,
              const float* __restrict__ bp,  float* __restrict__ out) {
    __nv_bfloat16* Xh = (__nv_bfloat16*)smem_;
    uint32_t sX = smem_u32(Xh);
    uint32_t sW = sX + 2 * WSZB;

    int tid = threadIdx.x, lane = tid & 31, w = tid >> 5;
    int wm = w >> 2, wn = w & 3;
    int g = lane >> 2, t2 = (lane & 3) * 2;
    size_t rowbase = (size_t)blockIdx.x * 128;

    loadWq(5, sW, tid);
    CP_COMMIT();

    // gather channel-major einsum output + LN over channels
    {
        int r = tid >> 2, e = tid & 3;
        const float* base = g_ecm + (size_t)(e * 32) * PLANE + rowbase + r;
        float v[32], s = 0.f, ss = 0.f;
        #pragma unroll
        for (int t = 0; t < 32; ++t) {
            float x = __ldg(base + (size_t)t * PLANE);
            v[t] = x; s += x; ss += x * x;
        }
        s  += __shfl_xor_sync(0xffffffffu, s, 1);
        s  += __shfl_xor_sync(0xffffffffu, s, 2);
        ss += __shfl_xor_sync(0xffffffffu, ss, 1);
        ss += __shfl_xor_sync(0xffffffffu, ss, 2);
        float mu = s * (1.0f / C);
        float rs = rsqrtf(ss * (1.0f / C) - mu * mu + 1e-5f);
        #pragma unroll
        for (int t = 0; t < 32; ++t) {
            int k = e * 32 + t;
            float xn = (v[t] - mu) * rs * __ldg(ga2 + k) + __ldg(be2 + k);
            __nv_bfloat16 h, l;
            split_bf16(xn, h, l);
            Xh[r * 136 + k] = h;
            Xh[WSZ + r * 136 + k] = l;
        }
    }
    CP_WAIT(0);
    __syncthreads();

    float acc[32];
    #pragma unroll
    for (int q = 0; q < 32; ++q) acc[q] = 0.f;
    wgemm16(sX, sW, lane, wm, wn, acc);

    #pragma unroll
    for (int ma = 0; ma < 2; ++ma) {
        size_t r0 = rowbase + wm*32 + ma*16 + g;
        float m0 = __ldg(mask + r0);
        float m1 = __ldg(mask + r0 + 8);
        #pragma unroll
        for (int na = 0; na < 4; ++na) {
            int idx = (ma*4 + na) * 4;
            int c0 = wn*32 + na*8 + t2;
            float b0 = __ldg(bp + c0), b1 = __ldg(bp + c0 + 1);
            float2 s0 = *(const float2*)(g_sg + r0 * C + c0);
            float2 s1 = *(const float2*)(g_sg + (r0 + 8) * C + c0);
            *(float2*)(out + r0 * C + c0) =
                make_float2((acc[idx+0] + b0) * s0.x * m0, (acc[idx+1] + b1) * s0.y * m0);
            *(float2*)(out + (r0 + 8) * C + c0) =
                make_float2((acc[idx+2] + b0) * s1.x * m1, (acc[idx+3] + b1) * s1.y * m1);
        }
    }
}

// ---------------------------------------------------------------------------
extern "C" void kernel_launch(void* const* d_in, const int* in_sizes, int n_in,
                              void* d_out, int out_size) {
    const float* x2d  = (const float*)d_in[0];
    const float* mask = (const float*)d_in[1];
    const float* ga1  = (const float*)d_in[2];
    const float* be1  = (const float*)d_in[3];
    const float* ga2  = (const float*)d_in[4];
    const float* be2  = (const float*)d_in[5];
    const float* Wi   = (const float*)d_in[6];
    const float* bi   = (const float*)d_in[7];
    const float* Wis  = (const float*)d_in[8];
    const float* bis  = (const float*)d_in[9];
    const float* Wj   = (const float*)d_in[10];
    const float* bj   = (const float*)d_in[11];
    const float* Wjs  = (const float*)d_in[12];
    const float* bjs  = (const float*)d_in[13];
    const float* Wp   = (const float*)d_in[14];
    const float* bp   = (const float*)d_in[15];
    const float* Ws   = (const float*)d_in[16];
    const float* bs   = (const float*)d_in[17];

    const int smem_s1 = 6 * WSZB;   // 208896
    const int smem_s3 = 4 * WSZB;   // 139264
    const int smem_e  = 2 * ECH;    // 81920
    cudaFuncSetAttribute(stage1_kernel, cudaFuncAttributeMaxDynamicSharedMemorySize, smem_s1);
    cudaFuncSetAttribute(stage3_kernel, cudaFuncAttributeMaxDynamicSharedMemorySize, smem_s3);
    cudaFuncSetAttribute(einsum_kernel, cudaFuncAttributeMaxDynamicSharedMemorySize, smem_e);

    convert_w_kernel<<<6, 256>>>(Wis, Wi, Wjs, Wj, Ws, Wp);

    stage1_kernel<<<NN / 128, 512, smem_s1>>>(x2d, mask, ga1, be1,
                                              bi, bis, bj, bjs, bs);

    dim3 grid2(NDIM / 128, NDIM / 128, C);
    einsum_kernel<<<grid2, 256, smem_e>>>();

    stage3_kernel<<<NN / 128, 512, smem_s3>>>(mask, ga2, be2, bp, (float*)d_out);
}

// round 6
// speedup vs baseline: 2.3181x; 1.0333x over previous
#include <cuda_runtime.h>
#include <cuda_bf16.h>
#include <cstdint>
#include <math.h>

#define NDIM 512
#define C 128
#define NN (NDIM*NDIM)
#define PLANE NN
#define WSZ 17408          // bf16 elems per 128x136 array
#define WSZB 34816         // bytes

// ---------------------------------------------------------------------------
// scratch
// ---------------------------------------------------------------------------
__device__ __align__(16) __nv_bfloat16 g_ihi[(size_t)C*NN];
__device__ __align__(16) __nv_bfloat16 g_ilo[(size_t)C*NN];
__device__ __align__(16) __nv_bfloat16 g_jhi[(size_t)C*NN];
__device__ __align__(16) __nv_bfloat16 g_jlo[(size_t)C*NN];
__device__ __align__(16) float g_ecm[(size_t)C*NN];
__device__ __align__(16) float g_sg [(size_t)NN*C];
// pre-split weights: [m][hi/lo][n][k], m: 0=Wis 1=Wi 2=Wjs 3=Wj 4=Ws 5=Wp
__device__ __align__(16) __nv_bfloat16 g_wq[6 * 2 * 128 * 128];

extern __shared__ char smem_[];

// ---------------------------------------------------------------------------
// PTX helpers (compute_103-portable)
// ---------------------------------------------------------------------------
__device__ __forceinline__ uint32_t smem_u32(const void* p) {
    uint32_t a;
    asm("{ .reg .u64 t; cvta.to.shared.u64 t, %1; cvt.u32.u64 %0, t; }" : "=r"(a) : "l"(p));
    return a;
}
__device__ __forceinline__ void ldm_x4(uint32_t addr, uint32_t* r) {
    asm volatile("ldmatrix.sync.aligned.m8n8.x4.shared.b16 {%0,%1,%2,%3}, [%4];"
        : "=r"(r[0]), "=r"(r[1]), "=r"(r[2]), "=r"(r[3]) : "r"(addr));
}
__device__ __forceinline__ void mma_bf16(float* d, const uint32_t* a, uint32_t b0, uint32_t b1) {
    asm volatile("mma.sync.aligned.m16n8k16.row.col.f32.bf16.bf16.f32 "
        "{%0,%1,%2,%3}, {%4,%5,%6,%7}, {%8,%9}, {%0,%1,%2,%3};"
        : "+f"(d[0]), "+f"(d[1]), "+f"(d[2]), "+f"(d[3])
        : "r"(a[0]), "r"(a[1]), "r"(a[2]), "r"(a[3]), "r"(b0), "r"(b1));
}
__device__ __forceinline__ void cp16(uint32_t dst, const void* src) {
    asm volatile("cp.async.cg.shared.global [%0], [%1], 16;" :: "r"(dst), "l"(src) : "memory");
}
#define CP_COMMIT() asm volatile("cp.async.commit_group;" ::: "memory")
#define CP_WAIT(n)  asm volatile("cp.async.wait_group %0;" :: "n"(n) : "memory")
__device__ __forceinline__ float sigmoidf_(float x) { return 1.0f / (1.0f + __expf(-x)); }
__device__ __forceinline__ void split_bf16(float v, __nv_bfloat16& h, __nv_bfloat16& l) {
    h = __float2bfloat16_rn(v);
    l = __float2bfloat16_rn(v - __bfloat162float(h));
}

// ---------------------------------------------------------------------------
// Prologue: split+transpose 6 weights
// ---------------------------------------------------------------------------
__global__ void convert_w_kernel(const float* __restrict__ Wis, const float* __restrict__ Wi,
                                 const float* __restrict__ Wjs, const float* __restrict__ Wj,
                                 const float* __restrict__ Ws,  const float* __restrict__ Wp) {
    const float* src[6] = {Wis, Wi, Wjs, Wj, Ws, Wp};
    const float* W = src[blockIdx.x];
    __nv_bfloat16* outh = g_wq + (size_t)blockIdx.x * 32768;
    __nv_bfloat16* outl = outh + 16384;
    for (int idx = threadIdx.x; idx < 16384; idx += blockDim.x) {
        int n = idx >> 7, k = idx & 127;
        float v = W[k * 128 + n];
        __nv_bfloat16 h, l;
        split_bf16(v, h, l);
        outh[n * 128 + k] = h;
        outl[n * 128 + k] = l;
    }
}

// cp.async weight pair (hi at sW, lo at sW+WSZB)
__device__ __forceinline__ void loadWq512(int m, uint32_t sW, int tid) {
    const char* src = (const char*)g_wq + (size_t)m * 65536;
    #pragma unroll
    for (int it = 0; it < 8; ++it) {
        int idx = tid + it * 512;
        int arr = idx >> 11, rem = idx & 2047;
        int row = rem >> 4, ch = rem & 15;
        cp16(sW + arr * WSZB + row * 272 + ch * 16,
             src + arr * 32768 + row * 256 + ch * 16);
    }
}
__device__ __forceinline__ void loadWq256(int m, uint32_t sW, int tid) {
    const char* src = (const char*)g_wq + (size_t)m * 65536;
    #pragma unroll
    for (int it = 0; it < 16; ++it) {
        int idx = tid + it * 256;
        int arr = idx >> 11, rem = idx & 2047;
        int row = rem >> 4, ch = rem & 15;
        cp16(sW + arr * WSZB + row * 272 + ch * 16,
             src + arr * 32768 + row * 256 + ch * 16);
    }
}

// ---------------------------------------------------------------------------
// warp GEMM (32x32 warp tile, K=128, row stride 272 B), 3-term split
// aLo/bLo = byte offset from hi array to lo array
// acc[(ma*4+na)*4+q]: q=0:(g,t2) 1:(g,t2+1) 2:(g+8,t2) 3:(g+8,t2+1)
// ---------------------------------------------------------------------------
__device__ __forceinline__ void wgemm16(uint32_t sA, uint32_t aLo,
                                        uint32_t sB, uint32_t bLo,
                                        int lane, int wm, int wn, float* acc) {
    int lr = lane & 7, sel = lane >> 3;
    uint32_t aRow = (uint32_t)((wm*32 + (sel & 1)*8 + lr) * 272 + (sel >> 1)*16);
    uint32_t bRow = (uint32_t)((wn*32 + (sel >> 1)*8 + lr) * 272 + (sel & 1)*16);
    #pragma unroll
    for (int kk = 0; kk < 8; ++kk) {
        uint32_t ah[2][4], al[2][4];
        #pragma unroll
        for (int ma = 0; ma < 2; ++ma) {
            uint32_t off = aRow + (uint32_t)(ma * 16 * 272 + kk * 32);
            ldm_x4(sA + off, ah[ma]);
            ldm_x4(sA + aLo + off, al[ma]);
        }
        #pragma unroll
        for (int p = 0; p < 2; ++p) {
            uint32_t bh[4], bl[4];
            uint32_t off = bRow + (uint32_t)(p * 16 * 272 + kk * 32);
            ldm_x4(sB + off, bh);
            ldm_x4(sB + bLo + off, bl);
            #pragma unroll
            for (int ma = 0; ma < 2; ++ma)
                #pragma unroll
                for (int h = 0; h < 2; ++h) {
                    float* d = acc + (ma*4 + p*2 + h)*4;
                    int s = h * 2;
                    mma_bf16(d, ah[ma], bh[s], bh[s+1]);
                    mma_bf16(d, ah[ma], bl[s], bl[s+1]);
                    mma_bf16(d, al[ma], bh[s], bh[s+1]);
                }
        }
    }
}

// dual-output variant: shared A fragments, two B matrices (gate W0, main W1)
__device__ __forceinline__ void wgemm_dual(uint32_t sA, uint32_t sW0, uint32_t sW1,
                                           int lane, int wm, int wn,
                                           float* accg, float* accm) {
    int lr = lane & 7, sel = lane >> 3;
    uint32_t aRow = (uint32_t)((wm*32 + (sel & 1)*8 + lr) * 272 + (sel >> 1)*16);
    uint32_t bRow = (uint32_t)((wn*32 + (sel >> 1)*8 + lr) * 272 + (sel & 1)*16);
    #pragma unroll
    for (int kk = 0; kk < 8; ++kk) {
        uint32_t ah[2][4], al[2][4];
        #pragma unroll
        for (int ma = 0; ma < 2; ++ma) {
            uint32_t off = aRow + (uint32_t)(ma * 16 * 272 + kk * 32);
            ldm_x4(sA + off, ah[ma]);
            ldm_x4(sA + WSZB + off, al[ma]);
        }
        #pragma unroll
        for (int p = 0; p < 2; ++p) {
            uint32_t off = bRow + (uint32_t)(p * 16 * 272 + kk * 32);
            uint32_t bh[4], bl[4];
            // gate
            ldm_x4(sW0 + off, bh);
            ldm_x4(sW0 + WSZB + off, bl);
            #pragma unroll
            for (int ma = 0; ma < 2; ++ma)
                #pragma unroll
                for (int h = 0; h < 2; ++h) {
                    float* d = accg + (ma*4 + p*2 + h)*4;
                    int s = h * 2;
                    mma_bf16(d, ah[ma], bh[s], bh[s+1]);
                    mma_bf16(d, ah[ma], bl[s], bl[s+1]);
                    mma_bf16(d, al[ma], bh[s], bh[s+1]);
                }
            // main
            ldm_x4(sW1 + off, bh);
            ldm_x4(sW1 + WSZB + off, bl);
            #pragma unroll
            for (int ma = 0; ma < 2; ++ma)
                #pragma unroll
                for (int h = 0; h < 2; ++h) {
                    float* d = accm + (ma*4 + p*2 + h)*4;
                    int s = h * 2;
                    mma_bf16(d, ah[ma], bh[s], bh[s+1]);
                    mma_bf16(d, ah[ma], bl[s], bl[s+1]);
                    mma_bf16(d, al[ma], bh[s], bh[s+1]);
                }
        }
    }
}

// ---------------------------------------------------------------------------
// Stage 1: LN(x) + 5 GEMMs (dual-fused), 512 threads, smem 208896 B
// ---------------------------------------------------------------------------
__global__ void __launch_bounds__(512, 1)
stage1_kernel(const float* __restrict__ x2d, const float* __restrict__ mask,
              const float* __restrict__ ga1, const float* __restrict__ be1,
              const float* __restrict__ bi,  const float* __restrict__ bis,
              const float* __restrict__ bj,  const float* __restrict__ bjs,
              const float* __restrict__ bs) {
    __nv_bfloat16* Xh = (__nv_bfloat16*)smem_;
    __nv_bfloat16* T1 = Xh + 4 * WSZ;       // W1 region doubles as staging
    uint32_t sX  = smem_u32(Xh);
    uint32_t sW0 = sX + 2 * WSZB;
    uint32_t sW1 = sX + 4 * WSZB;

    int tid = threadIdx.x, lane = tid & 31, w = tid >> 5;
    int wm = w >> 2, wn = w & 3;
    int g = lane >> 2, t2 = (lane & 3) * 2;
    size_t rowbase = (size_t)blockIdx.x * 128;

    loadWq512(0, sW0, tid); CP_COMMIT();   // Wis
    loadWq512(1, sW1, tid); CP_COMMIT();   // Wi

    // layernorm: 4 threads/row, 32 channels each
    {
        int r = tid >> 2, e = tid & 3;
        const float* xr = x2d + (rowbase + r) * C + e * 32;
        float v[32], s = 0.f, ss = 0.f;
        #pragma unroll
        for (int t = 0; t < 8; ++t) {
            float4 f = *(const float4*)(xr + t * 4);
            v[4*t+0]=f.x; v[4*t+1]=f.y; v[4*t+2]=f.z; v[4*t+3]=f.w;
            s += f.x + f.y + f.z + f.w;
            ss += f.x*f.x + f.y*f.y + f.z*f.z + f.w*f.w;
        }
        s  += __shfl_xor_sync(0xffffffffu, s, 1);
        s  += __shfl_xor_sync(0xffffffffu, s, 2);
        ss += __shfl_xor_sync(0xffffffffu, ss, 1);
        ss += __shfl_xor_sync(0xffffffffu, ss, 2);
        float mu = s * (1.0f / C);
        float rs = rsqrtf(ss * (1.0f / C) - mu * mu + 1e-5f);
        #pragma unroll
        for (int t = 0; t < 32; ++t) {
            int k = e * 32 + t;
            float xn = (v[t] - mu) * rs * __ldg(ga1 + k) + __ldg(be1 + k);
            __nv_bfloat16 h, l;
            split_bf16(xn, h, l);
            Xh[r * 136 + k] = h;
            Xh[WSZ + r * 136 + k] = l;
        }
    }

    float accg[32], accm[32];

    #pragma unroll 1
    for (int pass = 0; pass < 2; ++pass) {
        const float* bgp = pass ? bjs : bis;
        const float* bmp = pass ? bj  : bi;
        __nv_bfloat16* outh = pass ? g_jhi : g_ihi;
        __nv_bfloat16* outl = pass ? g_jlo : g_ilo;

        CP_WAIT(0);
        __syncthreads();
        #pragma unroll
        for (int q = 0; q < 32; ++q) { accg[q] = 0.f; accm[q] = 0.f; }
        wgemm_dual(sX, sW0, sW1, lane, wm, wn, accg, accm);
        __syncthreads();                       // done reading W0/W1
        loadWq512(pass ? 4 : 2, sW0, tid);     // prefetch next gate / Ws
        CP_COMMIT();

        // combine -> staging T1[col][row]
        #pragma unroll
        for (int ma = 0; ma < 2; ++ma) {
            int r0 = wm*32 + ma*16 + g;
            float m0 = __ldg(mask + rowbase + r0);
            float m1 = __ldg(mask + rowbase + r0 + 8);
            #pragma unroll
            for (int na = 0; na < 4; ++na) {
                int idx = (ma*4 + na) * 4;
                int c0 = wn*32 + na*8 + t2;
                float bg0 = __ldg(bgp + c0), bg1 = __ldg(bgp + c0 + 1);
                float b0 = __ldg(bmp + c0),  b1 = __ldg(bmp + c0 + 1);
                float v0 = (accm[idx+0] + b0) * sigmoidf_(accg[idx+0] + bg0) * m0;
                float v1 = (accm[idx+1] + b1) * sigmoidf_(accg[idx+1] + bg1) * m0;
                float v2 = (accm[idx+2] + b0) * sigmoidf_(accg[idx+2] + bg0) * m1;
                float v3 = (accm[idx+3] + b1) * sigmoidf_(accg[idx+3] + bg1) * m1;
                __nv_bfloat16 h, l;
                split_bf16(v0, h, l); T1[(c0  )*136 + r0    ] = h; T1[WSZ + (c0  )*136 + r0    ] = l;
                split_bf16(v1, h, l); T1[(c0+1)*136 + r0    ] = h; T1[WSZ + (c0+1)*136 + r0    ] = l;
                split_bf16(v2, h, l); T1[(c0  )*136 + r0 + 8] = h; T1[WSZ + (c0  )*136 + r0 + 8] = l;
                split_bf16(v3, h, l); T1[(c0+1)*136 + r0 + 8] = h; T1[WSZ + (c0+1)*136 + r0 + 8] = l;
            }
        }
        __syncthreads();

        // channel-major flush
        {
            int cch = tid >> 2, q = tid & 3;
            const uint4* srcH = (const uint4*)(T1 + cch * 136 + q * 32);
            const uint4* srcL = (const uint4*)(T1 + WSZ + cch * 136 + q * 32);
            uint4* dstH = (uint4*)(outh + (size_t)cch * PLANE + rowbase + q * 32);
            uint4* dstL = (uint4*)(outl + (size_t)cch * PLANE + rowbase + q * 32);
            #pragma unroll
            for (int t = 0; t < 4; ++t) { dstH[t] = srcH[t]; dstL[t] = srcL[t]; }
        }
        __syncthreads();
        if (pass == 0) { loadWq512(3, sW1, tid); CP_COMMIT(); }   // Wj
    }

    // sg = sigmoid(x@Ws+bs)
    CP_WAIT(0);
    __syncthreads();
    #pragma unroll
    for (int q = 0; q < 32; ++q) accg[q] = 0.f;
    wgemm16(sX, WSZB, sW0, WSZB, lane, wm, wn, accg);
    #pragma unroll
    for (int ma = 0; ma < 2; ++ma) {
        size_t r0 = rowbase + wm*32 + ma*16 + g;
        #pragma unroll
        for (int na = 0; na < 4; ++na) {
            int idx = (ma*4 + na) * 4;
            int c0 = wn*32 + na*8 + t2;
            float b0 = __ldg(bs + c0), b1 = __ldg(bs + c0 + 1);
            *(float2*)(g_sg + r0 * C + c0) =
                make_float2(sigmoidf_(accg[idx+0] + b0), sigmoidf_(accg[idx+1] + b1));
            *(float2*)(g_sg + (r0 + 8) * C + c0) =
                make_float2(sigmoidf_(accg[idx+2] + b0), sigmoidf_(accg[idx+3] + b1));
        }
    }
}

// ---------------------------------------------------------------------------
// Stage 2: einsum, block 128x256, 512 threads, 3-stage pipeline, 1 sync/chunk
// stage layout: Ah(128x80) Al Bh(256x80) Bl, stage size 61440 B, 3 stages
// ---------------------------------------------------------------------------
#define ESTG 61440

__device__ __forceinline__ void e_load(uint32_t sdst,
                                       const char* pAh, const char* pAl,
                                       const char* pBh, const char* pBl,
                                       int kb, int tid) {
    int gr = tid >> 2;
    uint32_t ch = (uint32_t)(tid & 3) * 16;
    size_t koff = (size_t)kb * 64 + ch;
    size_t ro = (size_t)gr * 1024;
    uint32_t so = (uint32_t)gr * 80 + ch;
    cp16(sdst +         so, pAh + ro + koff);
    cp16(sdst + 10240 + so, pAl + ro + koff);
    cp16(sdst + 20480 + so, pBh + ro + koff);
    cp16(sdst + 20480 + so + 128*80, pBh + ro + 128*1024 + koff);
    cp16(sdst + 40960 + so, pBl + ro + koff);
    cp16(sdst + 40960 + so + 128*80, pBl + ro + 128*1024 + koff);
}

__device__ __forceinline__ void e_mma(uint32_t st, int lane, int wm, int wn, float* acc) {
    int lr = lane & 7, sel = lane >> 3;
    uint32_t aRow = (uint32_t)((wm*32 + (sel & 1)*8 + lr) * 80 + (sel >> 1)*16);
    uint32_t bRow = (uint32_t)((wn*64 + (sel >> 1)*8 + lr) * 80 + (sel & 1)*16);
    uint32_t sAh = st, sAl = st + 10240, sBh = st + 20480, sBl = st + 40960;
    #pragma unroll
    for (int kk = 0; kk < 2; ++kk) {
        uint32_t ah[2][4], al[2][4];
        #pragma unroll
        for (int ma = 0; ma < 2; ++ma) {
            uint32_t off = aRow + (uint32_t)(ma * 16 * 80 + kk * 32);
            ldm_x4(sAh + off, ah[ma]);
            ldm_x4(sAl + off, al[ma]);
        }
        #pragma unroll
        for (int p = 0; p < 4; ++p) {
            uint32_t bh[4], bl[4];
            uint32_t off = bRow + (uint32_t)(p * 16 * 80 + kk * 32);
            ldm_x4(sBh + off, bh);
            ldm_x4(sBl + off, bl);
            #pragma unroll
            for (int ma = 0; ma < 2; ++ma)
                #pragma unroll
                for (int h = 0; h < 2; ++h) {
                    float* d = acc + (ma*8 + p*2 + h)*4;
                    int s = h * 2;
                    mma_bf16(d, ah[ma], bh[s], bh[s+1]);
                    mma_bf16(d, ah[ma], bl[s], bl[s+1]);
                    mma_bf16(d, al[ma], bh[s], bh[s+1]);
                }
        }
    }
}

__global__ void __launch_bounds__(512, 1)
einsum_kernel() {
    uint32_t sb = smem_u32(smem_);
    int tid = threadIdx.x, lane = tid & 31, w = tid >> 5;
    int wm = w >> 2, wn = w & 3;
    int g = lane >> 2, t2 = (lane & 3) * 2;
    int c = blockIdx.z;
    int ibase = blockIdx.x * 128, jbase = blockIdx.y * 256;

    size_t cpl = (size_t)c * PLANE * 2;
    const char* pAh = (const char*)g_ihi + cpl + (size_t)ibase * 1024;
    const char* pAl = (const char*)g_ilo + cpl + (size_t)ibase * 1024;
    const char* pBh = (const char*)g_jhi + cpl + (size_t)jbase * 1024;
    const char* pBl = (const char*)g_jlo + cpl + (size_t)jbase * 1024;

    float acc[64];
    #pragma unroll
    for (int q = 0; q < 64; ++q) acc[q] = 0.f;

    e_load(sb,        pAh, pAl, pBh, pBl, 0, tid); CP_COMMIT();
    e_load(sb + ESTG, pAh, pAl, pBh, pBl, 1, tid); CP_COMMIT();

    #pragma unroll 1
    for (int kb = 0; kb < 16; ++kb) {
        if (kb < 15) { CP_WAIT(1); } else { CP_WAIT(0); }
        __syncthreads();
        if (kb + 2 < 16) {
            e_load(sb + ((kb + 2) % 3) * ESTG, pAh, pAl, pBh, pBl, kb + 2, tid);
            CP_COMMIT();
        }
        e_mma(sb + (kb % 3) * ESTG, lane, wm, wn, acc);
    }

    float* O = g_ecm + (size_t)c * PLANE;
    #pragma unroll
    for (int ma = 0; ma < 2; ++ma) {
        size_t r0 = (size_t)(ibase + wm*32 + ma*16 + g);
        #pragma unroll
        for (int na = 0; na < 8; ++na) {
            int idx = (ma*8 + na) * 4;
            int c0 = jbase + wn*64 + na*8 + t2;
            *(float2*)(O + r0 * NDIM + c0)       = make_float2(acc[idx+0], acc[idx+1]);
            *(float2*)(O + (r0 + 8) * NDIM + c0) = make_float2(acc[idx+2], acc[idx+3]);
        }
    }
}

// ---------------------------------------------------------------------------
// Stage 3: 64-row blocks, 256 threads, 2 CTAs/SM, smem 104448 B
// ---------------------------------------------------------------------------
__global__ void __launch_bounds__(256, 2)
stage3_kernel(const float* __restrict__ mask,
              const float* __restrict__ ga2, const float* __restrict__ be2,
              const float* __restrict__ bp,  float* __restrict__ out) {
    __nv_bfloat16* Xh = (__nv_bfloat16*)smem_;       // 64x136 hi + 64x136 lo
    uint32_t sX = smem_u32(Xh);
    uint32_t sW = sX + WSZB;                         // weight pair (128x136 x2)

    int tid = threadIdx.x, lane = tid & 31, w = tid >> 5;
    int wm = w >> 2, wn = w & 3;
    int g = lane >> 2, t2 = (lane & 3) * 2;
    size_t rowbase = (size_t)blockIdx.x * 64;

    loadWq256(5, sW, tid);
    CP_COMMIT();

    // gather channel-major einsum output + LN over channels (64 rows)
    {
        int r = tid >> 2, e = tid & 3;
        const float* base = g_ecm + (size_t)(e * 32) * PLANE + rowbase + r;
        float v[32], s = 0.f, ss = 0.f;
        #pragma unroll
        for (int t = 0; t < 32; ++t) {
            float x = __ldg(base + (size_t)t * PLANE);
            v[t] = x; s += x; ss += x * x;
        }
        s  += __shfl_xor_sync(0xffffffffu, s, 1);
        s  += __shfl_xor_sync(0xffffffffu, s, 2);
        ss += __shfl_xor_sync(0xffffffffu, ss, 1);
        ss += __shfl_xor_sync(0xffffffffu, ss, 2);
        float mu = s * (1.0f / C);
        float rs = rsqrtf(ss * (1.0f / C) - mu * mu + 1e-5f);
        #pragma unroll
        for (int t = 0; t < 32; ++t) {
            int k = e * 32 + t;
            float xn = (v[t] - mu) * rs * __ldg(ga2 + k) + __ldg(be2 + k);
            __nv_bfloat16 h, l;
            split_bf16(xn, h, l);
            Xh[r * 136 + k] = h;
            Xh[8704 + r * 136 + k] = l;    // lo at +17408 B
        }
    }
    CP_WAIT(0);
    __syncthreads();

    float acc[32];
    #pragma unroll
    for (int q = 0; q < 32; ++q) acc[q] = 0.f;
    wgemm16(sX, 17408, sW, WSZB, lane, wm, wn, acc);

    #pragma unroll
    for (int ma = 0; ma < 2; ++ma) {
        size_t r0 = rowbase + wm*32 + ma*16 + g;
        float m0 = __ldg(mask + r0);
        float m1 = __ldg(mask + r0 + 8);
        #pragma unroll
        for (int na = 0; na < 4; ++na) {
            int idx = (ma*4 + na) * 4;
            int c0 = wn*32 + na*8 + t2;
            float b0 = __ldg(bp + c0), b1 = __ldg(bp + c0 + 1);
            float2 s0 = *(const float2*)(g_sg + r0 * C + c0);
            float2 s1 = *(const float2*)(g_sg + (r0 + 8) * C + c0);
            *(float2*)(out + r0 * C + c0) =
                make_float2((acc[idx+0] + b0) * s0.x * m0, (acc[idx+1] + b1) * s0.y * m0);
            *(float2*)(out + (r0 + 8) * C + c0) =
                make_float2((acc[idx+2] + b0) * s1.x * m1, (acc[idx+3] + b1) * s1.y * m1);
        }
    }
}

// ---------------------------------------------------------------------------
extern "C" void kernel_launch(void* const* d_in, const int* in_sizes, int n_in,
                              void* d_out, int out_size) {
    const float* x2d  = (const float*)d_in[0];
    const float* mask = (const float*)d_in[1];
    const float* ga1  = (const float*)d_in[2];
    const float* be1  = (const float*)d_in[3];
    const float* ga2  = (const float*)d_in[4];
    const float* be2  = (const float*)d_in[5];
    const float* Wi   = (const float*)d_in[6];
    const float* bi   = (const float*)d_in[7];
    const float* Wis  = (const float*)d_in[8];
    const float* bis  = (const float*)d_in[9];
    const float* Wj   = (const float*)d_in[10];
    const float* bj   = (const float*)d_in[11];
    const float* Wjs  = (const float*)d_in[12];
    const float* bjs  = (const float*)d_in[13];
    const float* Wp   = (const float*)d_in[14];
    const float* bp   = (const float*)d_in[15];
    const float* Ws   = (const float*)d_in[16];
    const float* bs   = (const float*)d_in[17];

    const int smem_s1 = 6 * WSZB;      // 208896
    const int smem_e  = 3 * ESTG;      // 184320
    const int smem_s3 = 3 * WSZB;      // 104448
    cudaFuncSetAttribute(stage1_kernel, cudaFuncAttributeMaxDynamicSharedMemorySize, smem_s1);
    cudaFuncSetAttribute(einsum_kernel, cudaFuncAttributeMaxDynamicSharedMemorySize, smem_e);
    cudaFuncSetAttribute(stage3_kernel, cudaFuncAttributeMaxDynamicSharedMemorySize, smem_s3);

    convert_w_kernel<<<6, 256>>>(Wis, Wi, Wjs, Wj, Ws, Wp);

    stage1_kernel<<<NN / 128, 512, smem_s1>>>(x2d, mask, ga1, be1,
                                              bi, bis, bj, bjs, bs);

    dim3 grid2(NDIM / 128, NDIM / 256, C);
    einsum_kernel<<<grid2, 512, smem_e>>>();

    stage3_kernel<<<NN / 64, 256, smem_s3>>>(mask, ga2, be2, bp, (float*)d_out);
}